// round 14
// baseline (speedup 1.0000x reference)
#include <cuda_runtime.h>
#include <cuda_bf16.h>
#include <cstdint>

static constexpr int B_ = 32, S_ = 128, E_ = 512, F_ = 2048;
static constexpr int KC = 32;    // K per chunk
static constexpr int MT = 256;   // M tile per CTA (warp tile m32 x n32)

// SMEM: B bf16 tiles (2 bufs x 8KB) | 3-deep fp32 A stage ring | ticket word
static constexpr int OFF_ST  = 16384;
static constexpr int STG_SZ  = 32768;
static constexpr int SM_TICK = 16384 + 3 * STG_SZ;          // 114688
static constexpr int SM_DYN  = SM_TICK + 128;               // 114816 -> 2 CTAs/SM

static constexpr int NT1 = (F_ / MT) * S_;                  // 1024 gemm1 tiles
static constexpr int NT2 = 2 * (E_ / MT) * S_ / 2 * 2;      // 512 gemm2 tiles (2 e x 2 kv x 128 s)
static constexpr int NTT = NT1 + 512;                       // 1536

// ---- scratch / sync ----
__device__ uint32_t g_H[(size_t)S_ * B_ * F_];      // packed (hi | lo<<16) [s][b][f]
__device__ float    g_P[2][(size_t)B_ * S_ * E_];   // gemm2 k-split partials [b][s][e]
__device__ int      g_tick;
__device__ int      g_f1[S_];

// ============ helpers ============
__device__ __forceinline__ uint32_t s2u(const void* p) {
    uint32_t a;
    asm("{ .reg .u64 t; cvta.to.shared.u64 t, %1; cvt.u32.u64 %0, t; }" : "=r"(a) : "l"(p));
    return a;
}
__device__ __forceinline__ uint32_t packbf(float lo, float hi) {   // lo -> low 16 bits
    uint32_t r; asm("cvt.rn.bf16x2.f32 %0, %1, %2;" : "=r"(r) : "f"(hi), "f"(lo)); return r;
}
__device__ __forceinline__ float bflo(uint32_t p) { return __uint_as_float(p << 16); }
__device__ __forceinline__ float bfhi(uint32_t p) { return __uint_as_float(p & 0xFFFF0000u); }
__device__ __forceinline__ void sts32(uint32_t a, uint32_t v) {
    asm volatile("st.shared.b32 [%0], %1;" :: "r"(a), "r"(v) : "memory");
}
__device__ __forceinline__ float ldsf(uint32_t a) {
    float v; asm volatile("ld.shared.f32 %0, [%1];" : "=f"(v) : "r"(a)); return v;
}
__device__ __forceinline__ void cpasync16(uint32_t saddr, const void* g) {
    asm volatile("cp.async.cg.shared.global [%0], [%1], 16;" :: "r"(saddr), "l"(g) : "memory");
}
__device__ __forceinline__ void cp_commit() {
    asm volatile("cp.async.commit_group;" ::: "memory");
}
__device__ __forceinline__ void cp_wait1() {
    asm volatile("cp.async.wait_group 1;" ::: "memory");
}
__device__ __forceinline__ void ldmB(uint32_t* r, uint32_t addr) {
    asm volatile("ldmatrix.sync.aligned.m8n8.x4.shared.b16 {%0,%1,%2,%3}, [%4];"
                 : "=r"(r[0]), "=r"(r[1]), "=r"(r[2]), "=r"(r[3]) : "r"(addr));
}
__device__ __forceinline__ void mma16816(float* c, const uint32_t* a, const uint32_t* b) {
    asm volatile(
        "mma.sync.aligned.m16n8k16.row.col.f32.bf16.bf16.f32 "
        "{%0,%1,%2,%3}, {%4,%5,%6,%7}, {%8,%9}, {%0,%1,%2,%3};"
        : "+f"(c[0]), "+f"(c[1]), "+f"(c[2]), "+f"(c[3])
        : "r"(a[0]), "r"(a[1]), "r"(a[2]), "r"(a[3]), "r"(b[0]), "r"(b[1]));
}
__device__ __forceinline__ uint32_t swz(uint32_t off) { return off ^ ((off >> 3) & 0x70); }
__device__ __forceinline__ uint32_t a_addr(int k, int m) {
    return (uint32_t)(k * 1024) + (((uint32_t)(m * 4)) ^ ((uint32_t)(k & 7) << 4));
}

__device__ __forceinline__ void cpA(const float* __restrict__ base, int ldw,
                                    uint32_t st, int t) {
#pragma unroll
    for (int j = 0; j < 8; j++) {
        const int id = j * 256 + t;
        const int kl = id >> 6, ir = id & 63;
        const uint32_t sa = st + (uint32_t)(kl * 1024)
                          + (((uint32_t)(ir * 16)) ^ ((uint32_t)(kl & 7) << 4));
        cpasync16(sa, base + (size_t)kl * ldw + ir * 4);
    }
    cp_commit();
}

__device__ __forceinline__ void loadAfrag(uint32_t st, int m_r, int k_c,
                                          uint32_t* ah, uint32_t* al) {
    float v0 = ldsf(st + a_addr(k_c,     m_r));
    float v1 = ldsf(st + a_addr(k_c + 1, m_r));
    float v2 = ldsf(st + a_addr(k_c,     m_r + 8));
    float v3 = ldsf(st + a_addr(k_c + 1, m_r + 8));
    float v4 = ldsf(st + a_addr(k_c + 8, m_r));
    float v5 = ldsf(st + a_addr(k_c + 9, m_r));
    float v6 = ldsf(st + a_addr(k_c + 8, m_r + 8));
    float v7 = ldsf(st + a_addr(k_c + 9, m_r + 8));
    ah[0] = packbf(v0, v1); ah[1] = packbf(v2, v3);
    ah[2] = packbf(v4, v5); ah[3] = packbf(v6, v7);
    al[0] = packbf(v0 - bflo(ah[0]), v1 - bfhi(ah[0]));
    al[1] = packbf(v2 - bflo(ah[1]), v3 - bfhi(ah[1]));
    al[2] = packbf(v4 - bflo(ah[2]), v5 - bfhi(ah[2]));
    al[3] = packbf(v6 - bflo(ah[3]), v7 - bfhi(ah[3]));
}

__device__ __forceinline__ void computeChunk(uint32_t bufB, uint32_t st,
                                             float acc[2][4][4], int L, int w) {
    const uint32_t bHi = bufB, bLo = bufB + 4096;
#pragma unroll
    for (int ks = 0; ks < 2; ks++) {
        uint32_t bh[8], bl[8];
#pragma unroll
        for (int P = 0; P < 2; P++) {
            const uint32_t n   = (uint32_t)(P * 16 + ((L >> 4) & 1) * 8 + (L & 7));
            const uint32_t off = n * 128 +
                (((uint32_t)(ks * 32 + ((L >> 3) & 1) * 16)) ^ ((uint32_t)(L & 7) << 4));
            ldmB(bh + P * 4, bHi + off);
            ldmB(bl + P * 4, bLo + off);
        }
#pragma unroll
        for (int mt = 0; mt < 2; mt++) {
            uint32_t ah[4], al[4];
            loadAfrag(st, w * 32 + mt * 16 + (L >> 2), ks * 16 + (L & 3) * 2, ah, al);
#pragma unroll
            for (int q = 0; q < 4; q++) {
                const uint32_t* Bh = bh + (q >> 1) * 4 + (q & 1) * 2;
                const uint32_t* Bl = bl + (q >> 1) * 4 + (q & 1) * 2;
                mma16816(acc[mt][q], ah, Bh);
                mma16816(acc[mt][q], ah, Bl);
                mma16816(acc[mt][q], al, Bh);
            }
        }
    }
}

// ============ tile bodies ============
__device__ __forceinline__ void tile_gemm1(uint32_t sb, int t, int w, int L,
                                           int s, int f0,
                                           const float* __restrict__ x,
                                           const float* __restrict__ W1,
                                           const float* __restrict__ b1) {
    float acc[2][4][4];
#pragma unroll
    for (int mt = 0; mt < 2; mt++)
#pragma unroll
        for (int q = 0; q < 4; q++)
#pragma unroll
            for (int r = 0; r < 4; r++) acc[mt][q][r] = 0.f;

    const float* Wb = W1 + (size_t)s * E_ * F_ + f0;
    const int bi = t >> 4, ep0 = (t & 15) * 2;

    auto ldB = [&](int c, float2* rb) {
#pragma unroll
        for (int i = 0; i < 2; i++)
            rb[i] = *(const float2*)(x + ((size_t)(bi + i * 16) * S_ + s) * E_ + c * KC + ep0);
    };
    auto stsB = [&](int sel, const float2* rb) {
        const uint32_t base = sb + (uint32_t)sel * 8192;
#pragma unroll
        for (int i = 0; i < 2; i++) {
            const uint32_t hp = packbf(rb[i].x, rb[i].y);
            const uint32_t lp = packbf(rb[i].x - bflo(hp), rb[i].y - bfhi(hp));
            const uint32_t off = swz((uint32_t)((bi + i * 16) * 128 + ep0 * 2));
            sts32(base + off, hp);
            sts32(base + 4096 + off, lp);
        }
    };

    float2 rb[2];
    cpA(Wb, F_, sb + OFF_ST, t);
    cpA(Wb + (size_t)KC * F_, F_, sb + OFF_ST + STG_SZ, t);
    ldB(0, rb);
    stsB(0, rb);
    ldB(1, rb);

    const int NC = E_ / KC;                             // 16
    for (int c = 0; c < NC; c++) {
        cp_wait1();
        __syncthreads();
        if (c + 2 < NC)
            cpA(Wb + (size_t)(c + 2) * KC * F_, F_, sb + OFF_ST + ((c + 2) % 3) * STG_SZ, t);
        else
            cp_commit();
        if (c + 1 < NC) {
            stsB((c + 1) & 1, rb);
            if (c + 2 < NC) ldB(c + 2, rb);
        }
        computeChunk(sb + (uint32_t)(c & 1) * 8192,
                     sb + OFF_ST + (c % 3) * STG_SZ, acc, L, w);
    }

#pragma unroll
    for (int mt = 0; mt < 2; mt++) {
        const int fr = f0 + w * 32 + mt * 16 + (L >> 2);
        const float bias0 = b1[s * F_ + fr];
        const float bias1 = b1[s * F_ + fr + 8];
#pragma unroll
        for (int q = 0; q < 4; q++) {
#pragma unroll
            for (int h = 0; h < 2; h++) {
#pragma unroll
                for (int p = 0; p < 2; p++) {
                    const float v = acc[mt][q][h * 2 + p] + (h ? bias1 : bias0);
                    const float hv = __bfloat162float(__float2bfloat16_rn(v));
                    const int b = q * 8 + (L & 3) * 2 + p;
                    const int f = fr + h * 8;
                    g_H[((size_t)s * B_ + b) * F_ + f] = packbf(v, v - hv);
                }
            }
        }
    }
}

__device__ __forceinline__ void tile_gemm2(uint32_t sb, int t, int w, int L,
                                           int s, int e0, int kv,
                                           const float* __restrict__ W2) {
    float acc[2][4][4];
#pragma unroll
    for (int mt = 0; mt < 2; mt++)
#pragma unroll
        for (int q = 0; q < 4; q++)
#pragma unroll
            for (int r = 0; r < 4; r++) acc[mt][q][r] = 0.f;

    const float* Wb = W2 + ((size_t)s * F_ + kv * (F_ / 2)) * E_ + e0;
    const int f_base = kv * (F_ / 2);
    const int bi = t >> 4, fp0 = (t & 15) * 2;

    auto ldB = [&](int c, uint2* rb) {
#pragma unroll
        for (int i = 0; i < 2; i++)
            rb[i] = *(const uint2*)(g_H + ((size_t)s * B_ + bi + i * 16) * F_
                                    + f_base + c * KC + fp0);
    };
    auto stsB = [&](int sel, const uint2* rb) {
        const uint32_t base = sb + (uint32_t)sel * 8192;
#pragma unroll
        for (int i = 0; i < 2; i++) {
            const uint32_t hp = (rb[i].x & 0xFFFFu) | (rb[i].y << 16);
            const uint32_t lp = (rb[i].x >> 16) | (rb[i].y & 0xFFFF0000u);
            const uint32_t off = swz((uint32_t)((bi + i * 16) * 128 + fp0 * 2));
            sts32(base + off, hp);
            sts32(base + 4096 + off, lp);
        }
    };

    uint2 rb[2];
    cpA(Wb, E_, sb + OFF_ST, t);
    cpA(Wb + (size_t)KC * E_, E_, sb + OFF_ST + STG_SZ, t);
    ldB(0, rb);
    stsB(0, rb);
    ldB(1, rb);

    const int NC = (F_ / 2) / KC;                       // 32
    for (int c = 0; c < NC; c++) {
        cp_wait1();
        __syncthreads();
        if (c + 2 < NC)
            cpA(Wb + (size_t)(c + 2) * KC * E_, E_, sb + OFF_ST + ((c + 2) % 3) * STG_SZ, t);
        else
            cp_commit();
        if (c + 1 < NC) {
            stsB((c + 1) & 1, rb);
            if (c + 2 < NC) ldB(c + 2, rb);
        }
        computeChunk(sb + (uint32_t)(c & 1) * 8192,
                     sb + OFF_ST + (c % 3) * STG_SZ, acc, L, w);
    }

    float* dst = g_P[kv];
#pragma unroll
    for (int mt = 0; mt < 2; mt++) {
        const int er = e0 + w * 32 + mt * 16 + (L >> 2);
#pragma unroll
        for (int q = 0; q < 4; q++) {
#pragma unroll
            for (int h = 0; h < 2; h++) {
#pragma unroll
                for (int p = 0; p < 2; p++) {
                    const int b = q * 8 + (L & 3) * 2 + p;
                    const int e = er + h * 8;
                    dst[((size_t)b * S_ + s) * E_ + e] = acc[mt][q][h * 2 + p];
                }
            }
        }
    }
}

// ============ kernels ============
__global__ void k_init() {
    if (threadIdx.x == 0) g_tick = 0;
    if (threadIdx.x < S_) g_f1[threadIdx.x] = 0;
}

__global__ __launch_bounds__(256, 2) void k_mlp(const float* __restrict__ x,
                                                const float* __restrict__ W1,
                                                const float* __restrict__ b1,
                                                const float* __restrict__ W2) {
    extern __shared__ char smraw[];
    const uint32_t sb = (s2u(smraw) + 127u) & ~127u;
    const int t = threadIdx.x, w = t >> 5, L = t & 31;

    for (;;) {
        if (t == 0) {
            const int tk = atomicAdd(&g_tick, 1);
            sts32(sb + SM_TICK, (uint32_t)tk);
        }
        __syncthreads();
        int tk;
        asm volatile("ld.shared.b32 %0, [%1];" : "=r"(tk) : "r"(sb + SM_TICK));
        if (tk >= NTT) break;

        if (tk < NT1) {
            const int s = tk >> 3, f0 = (tk & 7) * MT;
            tile_gemm1(sb, t, w, L, s, f0, x, W1, b1);
            __threadfence();
            __syncthreads();
            if (t == 0) atomicAdd(&g_f1[s], 1);
        } else {
            const int tk2 = tk - NT1;
            const int s = tk2 >> 2, e0 = (tk2 & 1) * MT, kv = (tk2 >> 1) & 1;
            if (t == 0) {
                int v;
                do {
                    asm volatile("ld.acquire.gpu.global.b32 %0, [%1];"
                                 : "=r"(v) : "l"(g_f1 + s) : "memory");
                    if (v < 8) __nanosleep(256);
                } while (v < 8);
            }
            __syncthreads();
            tile_gemm2(sb, t, w, L, s, e0, kv, W2);
        }
        __syncthreads();    // SMEM (ring/B/ticket) reuse guard across tiles
    }
}

__global__ void k_ln(const float* __restrict__ x, const float* __restrict__ b2,
                     const float* __restrict__ gamma, const float* __restrict__ beta,
                     float* __restrict__ out) {
    const int warp = threadIdx.x >> 5, lane = threadIdx.x & 31;
    const int row  = blockIdx.x * 8 + warp;
    const int s    = row & (S_ - 1);
    const size_t ro = (size_t)row * E_;

    float v[16];
    float sum = 0.f, sq = 0.f;
#pragma unroll
    for (int k = 0; k < 16; k++) {
        const int e = lane + 32 * k;
        const float tv = g_P[0][ro + e] + g_P[1][ro + e] + b2[s * E_ + e] + x[ro + e];
        v[k] = tv; sum += tv; sq += tv * tv;
    }
#pragma unroll
    for (int o = 16; o; o >>= 1) {
        sum += __shfl_xor_sync(0xFFFFFFFFu, sum, o);
        sq  += __shfl_xor_sync(0xFFFFFFFFu, sq,  o);
    }
    const float mu   = sum * (1.f / E_);
    const float var  = sq * (1.f / E_) - mu * mu;
    const float rstd = rsqrtf(var + 1e-5f);

    float* orow = out + ro;
#pragma unroll
    for (int k = 0; k < 16; k++) {
        const int e = lane + 32 * k;
        orow[e] = (v[k] - mu) * rstd * gamma[e] + beta[e];
    }
}

// ============================================================
extern "C" void kernel_launch(void* const* d_in, const int* in_sizes, int n_in,
                              void* d_out, int out_size) {
    const float* x     = (const float*)d_in[0];
    const float* W1    = (const float*)d_in[1];
    const float* b1    = (const float*)d_in[2];
    const float* W2    = (const float*)d_in[3];
    const float* b2    = (const float*)d_in[4];
    const float* gamma = (const float*)d_in[5];
    const float* beta  = (const float*)d_in[6];
    float* out = (float*)d_out;

    cudaFuncSetAttribute(k_mlp, cudaFuncAttributeMaxDynamicSharedMemorySize, SM_DYN);

    k_init<<<1, 128>>>();
    k_mlp<<<296, 256, SM_DYN>>>(x, W1, b1, W2);
    k_ln<<<(B_ * S_) / 8, 256>>>(x, b2, gamma, beta, out);
}